// round 3
// baseline (speedup 1.0000x reference)
#include <cuda_runtime.h>
#include <cstdint>

#define FULLMASK 0xFFFFFFFFu
#define TB   1024
#define TILE 256
#define ROWP 132   // Xs row stride (128 + pad) -> conflict-free strided reads
#define X2P  258   // x2s column stride -> conflict-free reads

// ---- device scratch (no allocations allowed) ----
__device__ float    g_polar[4096 * 6];   // zero-initialized at load; re-zeroed by finalize
__device__ unsigned g_done;              // zero-initialized; reset by finalize

__device__ __forceinline__ float sigmoidf_(float x) {
    return __fdividef(1.0f, 1.0f + __expf(-x));
}
__device__ __forceinline__ float2 unpack2_(unsigned long long a) {
    float2 r;
    r.x = __uint_as_float((unsigned)(a & 0xffffffffull));
    r.y = __uint_as_float((unsigned)(a >> 32));
    return r;
}
__device__ __forceinline__ unsigned long long dup2_(float x) {
    unsigned long long d;
    unsigned xb = __float_as_uint(x);
    asm("mov.b64 %0, {%1, %1};" : "=l"(d) : "r"(xb));
    return d;
}
__device__ __forceinline__ void ffma2_(unsigned long long& acc,
                                       unsigned long long a,
                                       unsigned long long b) {
    asm("fma.rn.f32x2 %0, %1, %2, %0;" : "+l"(acc) : "l"(a), "l"(b));
}

// smem layout (floats):
//   [0, 33792)        Xs: 256 x ROWP staged input tile (reused 3x)
//       sub-reuse in x2 phase: [0,20640)       x2s (80 x X2P transposed)
//                              [20736,25088)   gate (256 x 17)
//                              [25088,25344)   e0
//   [33792, 41984)    W_s1 (128 x 64)
//   [41984, 52224)    W2   (128 x 80) : cols 0..63 = W_e0, 64..79 = W_e0@W_g (folded per block)
//   [52224, 53248)    Wg   (64 x 16)  (staging for the fold)
//   [53248, 53376)    W_s2 (64 x 2)
//   [53376, 53888)    Wc   (32 x 16)  = W_e2 * W_o2
//   [53888, 53952)    W_o0 (64)
//   [53952, 54016)    b_s1 (64)
//   [54016, 54096)    b2   (80) : 0..63 = b_e0, 64..79 = b_e0@W_g + b_g
//   [54096, 54100)    misc: bs2[0], bs2[1], bo0
//   [54100, 54612)    sS   (256 x 2)
#define SM_FLOATS 54612

__global__ void __launch_bounds__(TB, 1)
main_kernel(const float* __restrict__ ns, const float* __restrict__ ne,
            const int* __restrict__ batch,
            const float* __restrict__ W1,  const float* __restrict__ b1,
            const float* __restrict__ Ws2, const float* __restrict__ bs2,
            const float* __restrict__ We0, const float* __restrict__ be0,
            const float* __restrict__ We2, const float* __restrict__ Wg,
            const float* __restrict__ bg,  const float* __restrict__ Wo0,
            const float* __restrict__ bo0, const float* __restrict__ Wo2,
            float* __restrict__ out, int Ntot, int G)
{
    extern __shared__ float sm[];
    float* Xs   = sm;
    float* sW1  = sm + 33792;
    float* sW2  = sm + 41984;
    float* sWg  = sm + 52224;
    float* sWs2 = sm + 53248;
    float* sWc  = sm + 53376;
    float* sWo0 = sm + 53888;
    float* sB1  = sm + 53952;
    float* sB2  = sm + 54016;
    float* sMisc= sm + 54096;
    float* sS   = sm + 54100;
    float* sGate= sm + 20736;   // inside Xs region (valid after GEMM2)
    float* sE0  = sm + 25088;   // inside Xs region

    const int tid  = threadIdx.x;
    const int n    = tid >> 3;     // 0..127 (node sub-index; also handles n+128)
    const int c    = tid & 7;      // 0..7   (column group)
    const int base = blockIdx.x * TILE;

    // ---- stage weights ----
    for (int i = tid; i < 8192; i += TB) sW1[i] = W1[i];
    for (int i = tid; i < 8192; i += TB) {
        int r = i >> 6, cc = i & 63;
        sW2[r * 80 + cc] = We0[i];
    }
    for (int i = tid; i < 1024; i += TB) sWg[i] = Wg[i];
    if (tid < 128) sWs2[tid] = Ws2[tid];
    if (tid < 512) sWc[tid] = We2[tid] * Wo2[tid & 15];
    if (tid < 64) { sWo0[tid] = Wo0[tid]; sB1[tid] = b1[tid]; sB2[tid] = be0[tid]; }
    if (tid == 0) { sMisc[0] = bs2[0]; sMisc[1] = bs2[1]; sMisc[2] = bo0[0]; }
    __syncthreads();

    // ---- per-block fold: W_e0 @ W_g into sW2 cols 64..79; bias fold ----
    {
        int r  = tid >> 3;           // 0..127
        int g0 = (tid & 7) * 2;      // 0,2,...,14
        float s0 = 0.f, s1 = 0.f;
        #pragma unroll 8
        for (int j = 0; j < 64; j++) {
            float x = sW2[r * 80 + j];
            float2 w = *(const float2*)&sWg[j * 16 + g0];
            s0 += x * w.x; s1 += x * w.y;
        }
        sW2[r * 80 + 64 + g0 + 0] = s0;
        sW2[r * 80 + 64 + g0 + 1] = s1;
        if (tid < 16) {
            float s = bg[tid];
            for (int j = 0; j < 64; j++) s += sB2[j] * sWg[j * 16 + tid];
            sB2[64 + tid] = s;
        }
    }

    // ---- stage node_scalar tile (float4, coalesced) ----
    for (int i = tid; i < TILE * 32; i += TB) {
        int node = i >> 5, q = i & 31;
        int gn = base + node;
        float4 v = (gn < Ntot) ? ((const float4*)ns)[gn * 32 + q]
                               : make_float4(0.f, 0.f, 0.f, 0.f);
        *(float4*)&Xs[node * ROWP + q * 4] = v;
    }
    __syncthreads();

    // ===================== GEMM1: ns @ W_s1 (64 cols) =====================
    unsigned long long acc1[2][4];
    #pragma unroll
    for (int i = 0; i < 2; i++)
        #pragma unroll
        for (int u = 0; u < 4; u++) acc1[i][u] = 0ull;

    #pragma unroll 4
    for (int k = 0; k < 128; k++) {
        unsigned long long w[4];
        #pragma unroll
        for (int u = 0; u < 4; u++)
            w[u] = *(const unsigned long long*)&sW1[k * 64 + 2 * c + 16 * u];
        #pragma unroll
        for (int i = 0; i < 2; i++) {
            unsigned long long xd = dup2_(Xs[(n + 128 * i) * ROWP + k]);
            #pragma unroll
            for (int u = 0; u < 4; u++) ffma2_(acc1[i][u], w[u], xd);
        }
    }
    __syncthreads();   // all Xs reads done before reload

    // ---- epilogue 1: s = silu(h1) @ W_s2 + b_s2 ----
    #pragma unroll
    for (int i = 0; i < 2; i++) {
        float sp0 = 0.f, sp1 = 0.f;
        #pragma unroll
        for (int u = 0; u < 4; u++) {
            int col = 2 * c + 16 * u;
            float2 h2 = unpack2_(acc1[i][u]);
            float h = h2.x + sB1[col];
            float hs = h * sigmoidf_(h);
            sp0 += hs * sWs2[col * 2 + 0];
            sp1 += hs * sWs2[col * 2 + 1];
            h = h2.y + sB1[col + 1];
            hs = h * sigmoidf_(h);
            sp0 += hs * sWs2[(col + 1) * 2 + 0];
            sp1 += hs * sWs2[(col + 1) * 2 + 1];
        }
        #pragma unroll
        for (int o = 1; o < 8; o <<= 1) {
            sp0 += __shfl_xor_sync(FULLMASK, sp0, o);
            sp1 += __shfl_xor_sync(FULLMASK, sp1, o);
        }
        if (c == 0) {
            int node = n + 128 * i;
            sS[node * 2 + 0] = sp0 + sMisc[0];
            sS[node * 2 + 1] = sp1 + sMisc[1];
        }
    }

    // ---- stage x0 tile (node_equi cols 0..127) ----
    for (int i = tid; i < TILE * 32; i += TB) {
        int node = i >> 5, q = i & 31;
        int gn = base + node;
        float4 v = (gn < Ntot) ? ((const float4*)ne)[gn * 120 + q]
                               : make_float4(0.f, 0.f, 0.f, 0.f);
        *(float4*)&Xs[node * ROWP + q * 4] = v;
    }
    __syncthreads();

    // ===================== GEMM2: x0 @ [W_e0 | W_e0@W_g] (80 cols) =====================
    unsigned long long acc2[2][5];
    #pragma unroll
    for (int i = 0; i < 2; i++)
        #pragma unroll
        for (int u = 0; u < 5; u++) acc2[i][u] = 0ull;

    #pragma unroll 4
    for (int k = 0; k < 128; k++) {
        unsigned long long w[5];
        #pragma unroll
        for (int u = 0; u < 5; u++)
            w[u] = *(const unsigned long long*)&sW2[k * 80 + 2 * c + 16 * u];
        #pragma unroll
        for (int i = 0; i < 2; i++) {
            unsigned long long xd = dup2_(Xs[(n + 128 * i) * ROWP + k]);
            #pragma unroll
            for (int u = 0; u < 5; u++) ffma2_(acc2[i][u], w[u], xd);
        }
    }
    __syncthreads();   // all Xs reads done before gate/e0 writes into Xs region

    // ---- epilogue 2: e0 partial + gate (gate cols fully owned per thread) ----
    #pragma unroll
    for (int i = 0; i < 2; i++) {
        int node = n + 128 * i;
        float e0p = 0.f;
        #pragma unroll
        for (int u = 0; u < 4; u++) {
            int col = 2 * c + 16 * u;
            float2 h2 = unpack2_(acc2[i][u]);
            float h = h2.x + sB2[col];
            e0p += (h * sigmoidf_(h)) * sWo0[col];
            h = h2.y + sB2[col + 1];
            e0p += (h * sigmoidf_(h)) * sWo0[col + 1];
        }
        {
            float2 gp = unpack2_(acc2[i][4]);
            sGate[node * 17 + 2 * c]     = sigmoidf_(gp.x + sB2[64 + 2 * c]);
            sGate[node * 17 + 2 * c + 1] = sigmoidf_(gp.y + sB2[64 + 2 * c + 1]);
        }
        #pragma unroll
        for (int o = 1; o < 8; o <<= 1)
            e0p += __shfl_xor_sync(FULLMASK, e0p, o);
        if (c == 0) sE0[node] = e0p + sMisc[2];
    }
    __syncthreads();

    // ===================== x2 contraction: e2[v] = sum_m x2[m,v] * g2[m] =====================
    // 4 threads per node; quarters split the m-range 4 ways.
    const int node = tid >> 2;
    const int quad = tid & 3;
    float gr[16];
    #pragma unroll
    for (int h = 0; h < 16; h++) gr[h] = sGate[node * 17 + h];

    float e2[5] = {0.f, 0.f, 0.f, 0.f, 0.f};
    const int gnode = base + node;
    const bool valid = (gnode < Ntot);

    #pragma unroll
    for (int chunk = 0; chunk < 2; chunk++) {
        // cooperative transposed stage: x2s[col][node], 80 cols of this chunk (float4 loads)
        for (int i = tid; i < TILE * 20; i += TB) {
            int nd   = i / 20;
            int col4 = i - nd * 20;
            int gn   = base + nd;
            float4 v = (gn < Ntot)
                ? ((const float4*)ne)[gn * 120 + 80 + chunk * 20 + col4]
                : make_float4(0.f, 0.f, 0.f, 0.f);
            Xs[(col4 * 4 + 0) * X2P + nd] = v.x;
            Xs[(col4 * 4 + 1) * X2P + nd] = v.y;
            Xs[(col4 * 4 + 2) * X2P + nd] = v.z;
            Xs[(col4 * 4 + 3) * X2P + nd] = v.w;
        }
        __syncthreads();
        #pragma unroll
        for (int mm = 0; mm < 4; mm++) {
            int ml = quad * 4 + mm;              // local m within chunk (0..15)
            int m  = chunk * 16 + ml;            // global m (0..31)
            const float4* wc = (const float4*)&sWc[m * 16];
            float4 w0 = wc[0], w1 = wc[1], w2 = wc[2], w3 = wc[3];
            float g2m = gr[0] * w0.x + gr[1] * w0.y + gr[2] * w0.z + gr[3] * w0.w
                      + gr[4] * w1.x + gr[5] * w1.y + gr[6] * w1.z + gr[7] * w1.w
                      + gr[8] * w2.x + gr[9] * w2.y + gr[10]* w2.z + gr[11]* w2.w
                      + gr[12]* w3.x + gr[13]* w3.y + gr[14]* w3.z + gr[15]* w3.w;
            #pragma unroll
            for (int v = 0; v < 5; v++)
                e2[v] += Xs[(ml * 5 + v) * X2P + node] * g2m;
        }
        __syncthreads();   // chunk reads done before restage
    }
    // combine the four m-quarters within the thread quad
    #pragma unroll
    for (int v = 0; v < 5; v++) {
        e2[v] += __shfl_xor_sync(FULLMASK, e2[v], 1);
        e2[v] += __shfl_xor_sync(FULLMASK, e2[v], 2);
    }

    // ---- per-node source vector + segment sum ----
    float s0 = sS[node * 2 + 0];
    float s1 = sS[node * 2 + 1];
    float e0 = sE0[node];
    float v6[6];
    v6[0] = valid ? (e0 * s0) : 0.f;
    #pragma unroll
    for (int v = 0; v < 5; v++) v6[v + 1] = valid ? (e2[v] * s1) : 0.f;

    int g  = valid ? batch[gnode] : -1;
    int g0 = __shfl_sync(FULLMASK, g, 0);
    bool uni = __all_sync(FULLMASK, g == g0);
    if (uni) {
        #pragma unroll
        for (int d = 0; d < 6; d++) {
            float t = quad ? 0.f : v6[d];   // avoid quadruple count across lane quads
            #pragma unroll
            for (int o = 16; o > 0; o >>= 1) t += __shfl_xor_sync(FULLMASK, t, o);
            if ((tid & 31) == 0 && g0 >= 0) atomicAdd(&g_polar[g0 * 6 + d], t);
        }
    } else if (g >= 0 && quad == 0) {
        #pragma unroll
        for (int d = 0; d < 6; d++) atomicAdd(&g_polar[g * 6 + d], v6[d]);
    }

    // ===================== last-block finalize =====================
    __shared__ unsigned s_ticket;
    __threadfence();
    __syncthreads();
    if (tid == 0) s_ticket = atomicAdd(&g_done, 1u);
    __syncthreads();
    if (s_ticket == gridDim.x - 1) {
        __threadfence();
        for (int gg = tid; gg < G; gg += TB) {
            float zero  = g_polar[gg * 6 + 0];
            float dxy   = g_polar[gg * 6 + 1];
            float dyz   = g_polar[gg * 6 + 2];
            float dz2   = g_polar[gg * 6 + 3];
            float dzx   = g_polar[gg * 6 + 4];
            float dx2y2 = g_polar[gg * 6 + 5];
            float dn = sqrtf(dxy*dxy + dyz*dyz + dz2*dz2 + dzx*dzx + dx2y2*dx2y2);
            const float cc = 0.5773502691896258f;
            float a00 = zero + cc * (dn - dz2) + dx2y2;
            float a11 = zero + cc * (dn - dz2) - dx2y2;
            float a22 = zero + cc * (dn + 2.0f * dz2);
            out[gg * 9 + 0] = a00; out[gg * 9 + 1] = dxy; out[gg * 9 + 2] = dzx;
            out[gg * 9 + 3] = dxy; out[gg * 9 + 4] = a11; out[gg * 9 + 5] = dyz;
            out[gg * 9 + 6] = dzx; out[gg * 9 + 7] = dyz; out[gg * 9 + 8] = a22;
            #pragma unroll
            for (int d = 0; d < 6; d++) g_polar[gg * 6 + d] = 0.f;  // reset for next call
        }
        if (tid == 0) g_done = 0;  // reset ticket for next call
    }
}

// ================= launch =================
extern "C" void kernel_launch(void* const* d_in, const int* in_sizes, int n_in,
                              void* d_out, int out_size)
{
    const float* ns    = (const float*)d_in[0];
    const float* ne    = (const float*)d_in[1];
    const int*   batch = (const int*)d_in[2];
    // n_graphs may or may not be materialized as a scalar input: detect by size.
    int wb = (n_in > 3 && in_sizes[3] == 128 * 64) ? 3 : 4;
    const float* W_s1 = (const float*)d_in[wb + 0];
    const float* b_s1 = (const float*)d_in[wb + 1];
    const float* W_s2 = (const float*)d_in[wb + 2];
    const float* b_s2 = (const float*)d_in[wb + 3];
    const float* W_e0 = (const float*)d_in[wb + 4];
    const float* b_e0 = (const float*)d_in[wb + 5];
    const float* W_e2 = (const float*)d_in[wb + 6];
    const float* W_g  = (const float*)d_in[wb + 7];
    const float* b_g  = (const float*)d_in[wb + 8];
    const float* W_o0 = (const float*)d_in[wb + 9];
    const float* b_o0 = (const float*)d_in[wb + 10];
    const float* W_o2 = (const float*)d_in[wb + 11];

    int N = in_sizes[0] / 128;
    int G = out_size / 9;

    size_t smemBytes = (size_t)SM_FLOATS * sizeof(float);
    cudaFuncSetAttribute(main_kernel, cudaFuncAttributeMaxDynamicSharedMemorySize,
                         (int)smemBytes);
    int blocks = (N + TILE - 1) / TILE;
    main_kernel<<<blocks, TB, smemBytes>>>(ns, ne, batch, W_s1, b_s1,
                                           W_s2, b_s2, W_e0, b_e0, W_e2,
                                           W_g, b_g, W_o0, b_o0, W_o2,
                                           (float*)d_out, N, G);
}

// round 4
// speedup vs baseline: 1.2067x; 1.2067x over previous
#include <cuda_runtime.h>
#include <cstdint>

#define FULLMASK 0xFFFFFFFFu
#define TB   512
#define TILE 256
#define ROWP 132   // Xs row stride (128 + pad) -> conflict-free strided reads
#define X2P  258   // x2s column stride -> conflict-free reads

// ---- device scratch (no allocations allowed) ----
__device__ float    g_polar[4096 * 6];   // zero-initialized at load; re-zeroed by finalize
__device__ unsigned g_done;              // zero-initialized; reset by finalize

__device__ __forceinline__ float sigmoidf_(float x) {
    return __fdividef(1.0f, 1.0f + __expf(-x));
}
__device__ __forceinline__ float2 unpack2_(unsigned long long a) {
    float2 r;
    r.x = __uint_as_float((unsigned)(a & 0xffffffffull));
    r.y = __uint_as_float((unsigned)(a >> 32));
    return r;
}
__device__ __forceinline__ unsigned long long dup2_(float x) {
    unsigned long long d;
    unsigned xb = __float_as_uint(x);
    asm("mov.b64 %0, {%1, %1};" : "=l"(d) : "r"(xb));
    return d;
}
__device__ __forceinline__ void ffma2_(unsigned long long& acc,
                                       unsigned long long a,
                                       unsigned long long b) {
    asm("fma.rn.f32x2 %0, %1, %2, %0;" : "+l"(acc) : "l"(a), "l"(b));
}

// smem layout (floats): same as R2
#define SM_FLOATS 54612

__global__ void __launch_bounds__(TB, 1)
main_kernel(const float* __restrict__ ns, const float* __restrict__ ne,
            const int* __restrict__ batch,
            const float* __restrict__ W1,  const float* __restrict__ b1,
            const float* __restrict__ Ws2, const float* __restrict__ bs2,
            const float* __restrict__ We0, const float* __restrict__ be0,
            const float* __restrict__ We2, const float* __restrict__ Wg,
            const float* __restrict__ bg,  const float* __restrict__ Wo0,
            const float* __restrict__ bo0, const float* __restrict__ Wo2,
            float* __restrict__ out, int Ntot, int G)
{
    extern __shared__ float sm[];
    float* Xs   = sm;
    float* sW1  = sm + 33792;
    float* sW2  = sm + 41984;
    float* sWg  = sm + 52224;
    float* sWs2 = sm + 53248;
    float* sWc  = sm + 53376;
    float* sWo0 = sm + 53888;
    float* sB1  = sm + 53952;
    float* sB2  = sm + 54016;
    float* sMisc= sm + 54096;
    float* sS   = sm + 54100;
    float* sGate= sm + 20736;   // inside Xs region (valid after GEMM2)
    float* sE0  = sm + 25088;   // inside Xs region

    const int tid  = threadIdx.x;
    const int n    = tid >> 3;     // 0..63  (node sub-index)
    const int c    = tid & 7;      // 0..7   (column group: owns cols 4c..4c+3, 32+4c..32+4c+3)
    const int base = blockIdx.x * TILE;

    // ---- stage weights ----
    for (int i = tid; i < 8192; i += TB) sW1[i] = W1[i];
    for (int i = tid; i < 8192; i += TB) {
        int r = i >> 6, cc = i & 63;
        sW2[r * 80 + cc] = We0[i];
    }
    for (int i = tid; i < 1024; i += TB) sWg[i] = Wg[i];
    if (tid < 128) sWs2[tid] = Ws2[tid];
    if (tid < 512) sWc[tid] = We2[tid] * Wo2[tid & 15];
    if (tid < 64) { sWo0[tid] = Wo0[tid]; sB1[tid] = b1[tid]; sB2[tid] = be0[tid]; }
    if (tid == 0) { sMisc[0] = bs2[0]; sMisc[1] = bs2[1]; sMisc[2] = bo0[0]; }
    __syncthreads();

    // ---- per-block fold: W_e0 @ W_g into sW2 cols 64..79; bias fold ----
    {
        int r  = tid >> 2;           // 0..127
        int g0 = (tid & 3) * 4;      // 0,4,8,12
        float s0 = 0.f, s1 = 0.f, s2 = 0.f, s3 = 0.f;
        #pragma unroll 8
        for (int j = 0; j < 64; j++) {
            float x = sW2[r * 80 + j];
            float4 w = *(const float4*)&sWg[j * 16 + g0];
            s0 += x * w.x; s1 += x * w.y; s2 += x * w.z; s3 += x * w.w;
        }
        sW2[r * 80 + 64 + g0 + 0] = s0;
        sW2[r * 80 + 64 + g0 + 1] = s1;
        sW2[r * 80 + 64 + g0 + 2] = s2;
        sW2[r * 80 + 64 + g0 + 3] = s3;
        if (tid < 16) {
            float s = bg[tid];
            for (int j = 0; j < 64; j++) s += sB2[j] * sWg[j * 16 + tid];
            sB2[64 + tid] = s;
        }
    }

    // ---- stage node_scalar tile (float4, coalesced) ----
    for (int i = tid; i < TILE * 32; i += TB) {
        int node = i >> 5, q = i & 31;
        int gn = base + node;
        float4 v = (gn < Ntot) ? ((const float4*)ns)[gn * 32 + q]
                               : make_float4(0.f, 0.f, 0.f, 0.f);
        *(float4*)&Xs[node * ROWP + q * 4] = v;
    }
    __syncthreads();

    // ===================== GEMM1: ns @ W_s1 (64 cols) =====================
    // acc1[i][2g+p] holds col pair (4c + 32g + 2p, +1) for node n + 64*i
    unsigned long long acc1[4][4];
    #pragma unroll
    for (int i = 0; i < 4; i++)
        #pragma unroll
        for (int u = 0; u < 4; u++) acc1[i][u] = 0ull;

    #pragma unroll 4
    for (int k2 = 0; k2 < 128; k2 += 2) {
        ulonglong2 w00 = *(const ulonglong2*)&sW1[k2 * 64 + 4 * c];
        ulonglong2 w01 = *(const ulonglong2*)&sW1[k2 * 64 + 4 * c + 32];
        ulonglong2 w10 = *(const ulonglong2*)&sW1[(k2 + 1) * 64 + 4 * c];
        ulonglong2 w11 = *(const ulonglong2*)&sW1[(k2 + 1) * 64 + 4 * c + 32];
        #pragma unroll
        for (int i = 0; i < 4; i++) {
            float2 xp = *(const float2*)&Xs[(n + 64 * i) * ROWP + k2];
            unsigned long long x0 = dup2_(xp.x);
            unsigned long long x1 = dup2_(xp.y);
            ffma2_(acc1[i][0], w00.x, x0);
            ffma2_(acc1[i][1], w00.y, x0);
            ffma2_(acc1[i][2], w01.x, x0);
            ffma2_(acc1[i][3], w01.y, x0);
            ffma2_(acc1[i][0], w10.x, x1);
            ffma2_(acc1[i][1], w10.y, x1);
            ffma2_(acc1[i][2], w11.x, x1);
            ffma2_(acc1[i][3], w11.y, x1);
        }
    }
    __syncthreads();   // all Xs reads done before reload

    // ---- epilogue 1: s = silu(h1) @ W_s2 + b_s2 ----
    #pragma unroll
    for (int i = 0; i < 4; i++) {
        float sp0 = 0.f, sp1 = 0.f;
        #pragma unroll
        for (int u = 0; u < 4; u++) {
            int col = 4 * c + 32 * (u >> 1) + 2 * (u & 1);
            float2 h2 = unpack2_(acc1[i][u]);
            float h = h2.x + sB1[col];
            float hs = h * sigmoidf_(h);
            sp0 += hs * sWs2[col * 2 + 0];
            sp1 += hs * sWs2[col * 2 + 1];
            h = h2.y + sB1[col + 1];
            hs = h * sigmoidf_(h);
            sp0 += hs * sWs2[(col + 1) * 2 + 0];
            sp1 += hs * sWs2[(col + 1) * 2 + 1];
        }
        #pragma unroll
        for (int o = 1; o < 8; o <<= 1) {
            sp0 += __shfl_xor_sync(FULLMASK, sp0, o);
            sp1 += __shfl_xor_sync(FULLMASK, sp1, o);
        }
        if (c == 0) {
            int node = n + 64 * i;
            sS[node * 2 + 0] = sp0 + sMisc[0];
            sS[node * 2 + 1] = sp1 + sMisc[1];
        }
    }

    // ---- stage x0 tile (node_equi cols 0..127) ----
    for (int i = tid; i < TILE * 32; i += TB) {
        int node = i >> 5, q = i & 31;
        int gn = base + node;
        float4 v = (gn < Ntot) ? ((const float4*)ne)[gn * 120 + q]
                               : make_float4(0.f, 0.f, 0.f, 0.f);
        *(float4*)&Xs[node * ROWP + q * 4] = v;
    }
    __syncthreads();

    // ===================== GEMM2: x0 @ [W_e0 | W_e0@W_g] (80 cols) =====================
    // acc2[i][2g+p]: col pair (4c+32g+2p, +1); acc2[i][4]: gate pair (64+2c, +1)
    unsigned long long acc2[4][5];
    #pragma unroll
    for (int i = 0; i < 4; i++)
        #pragma unroll
        for (int u = 0; u < 5; u++) acc2[i][u] = 0ull;

    #pragma unroll 2
    for (int k2 = 0; k2 < 128; k2 += 2) {
        ulonglong2 w00 = *(const ulonglong2*)&sW2[k2 * 80 + 4 * c];
        ulonglong2 w01 = *(const ulonglong2*)&sW2[k2 * 80 + 4 * c + 32];
        unsigned long long wg0 = *(const unsigned long long*)&sW2[k2 * 80 + 64 + 2 * c];
        ulonglong2 w10 = *(const ulonglong2*)&sW2[(k2 + 1) * 80 + 4 * c];
        ulonglong2 w11 = *(const ulonglong2*)&sW2[(k2 + 1) * 80 + 4 * c + 32];
        unsigned long long wg1 = *(const unsigned long long*)&sW2[(k2 + 1) * 80 + 64 + 2 * c];
        #pragma unroll
        for (int i = 0; i < 4; i++) {
            float2 xp = *(const float2*)&Xs[(n + 64 * i) * ROWP + k2];
            unsigned long long x0 = dup2_(xp.x);
            unsigned long long x1 = dup2_(xp.y);
            ffma2_(acc2[i][0], w00.x, x0);
            ffma2_(acc2[i][1], w00.y, x0);
            ffma2_(acc2[i][2], w01.x, x0);
            ffma2_(acc2[i][3], w01.y, x0);
            ffma2_(acc2[i][4], wg0,   x0);
            ffma2_(acc2[i][0], w10.x, x1);
            ffma2_(acc2[i][1], w10.y, x1);
            ffma2_(acc2[i][2], w11.x, x1);
            ffma2_(acc2[i][3], w11.y, x1);
            ffma2_(acc2[i][4], wg1,   x1);
        }
    }
    __syncthreads();   // all Xs reads done before gate/e0 writes into Xs region

    // ---- epilogue 2: e0 partial + gate (gate cols fully owned per thread) ----
    #pragma unroll
    for (int i = 0; i < 4; i++) {
        int node = n + 64 * i;
        float e0p = 0.f;
        #pragma unroll
        for (int u = 0; u < 4; u++) {
            int col = 4 * c + 32 * (u >> 1) + 2 * (u & 1);
            float2 h2 = unpack2_(acc2[i][u]);
            float h = h2.x + sB2[col];
            e0p += (h * sigmoidf_(h)) * sWo0[col];
            h = h2.y + sB2[col + 1];
            e0p += (h * sigmoidf_(h)) * sWo0[col + 1];
        }
        {
            float2 gp = unpack2_(acc2[i][4]);
            sGate[node * 17 + 2 * c]     = sigmoidf_(gp.x + sB2[64 + 2 * c]);
            sGate[node * 17 + 2 * c + 1] = sigmoidf_(gp.y + sB2[64 + 2 * c + 1]);
        }
        #pragma unroll
        for (int o = 1; o < 8; o <<= 1)
            e0p += __shfl_xor_sync(FULLMASK, e0p, o);
        if (c == 0) sE0[node] = e0p + sMisc[2];
    }
    __syncthreads();

    // ===================== x2 contraction: e2[v] = sum_m x2[m,v] * g2[m] =====================
    // Thread pair (2t, 2t+1) shares node t; halves split the m-range.
    const int node = tid >> 1;
    const int half = tid & 1;
    float gr[16];
    #pragma unroll
    for (int h = 0; h < 16; h++) gr[h] = sGate[node * 17 + h];

    float e2[5] = {0.f, 0.f, 0.f, 0.f, 0.f};
    const int gnode = base + node;
    const bool valid = (gnode < Ntot);

    #pragma unroll
    for (int chunk = 0; chunk < 2; chunk++) {
        // cooperative transposed stage: x2s[col][node], 80 cols of this chunk (float4 loads)
        for (int i = tid; i < TILE * 20; i += TB) {
            int nd   = i / 20;
            int col4 = i - nd * 20;
            int gn   = base + nd;
            float4 v = (gn < Ntot)
                ? ((const float4*)ne)[gn * 120 + 80 + chunk * 20 + col4]
                : make_float4(0.f, 0.f, 0.f, 0.f);
            Xs[(col4 * 4 + 0) * X2P + nd] = v.x;
            Xs[(col4 * 4 + 1) * X2P + nd] = v.y;
            Xs[(col4 * 4 + 2) * X2P + nd] = v.z;
            Xs[(col4 * 4 + 3) * X2P + nd] = v.w;
        }
        __syncthreads();
        #pragma unroll
        for (int mm = 0; mm < 8; mm++) {
            int ml = half * 8 + mm;              // local m within chunk (0..15)
            int m  = chunk * 16 + ml;            // global m (0..31)
            const float4* wc = (const float4*)&sWc[m * 16];
            float4 w0 = wc[0], w1 = wc[1], w2 = wc[2], w3 = wc[3];
            float g2m = gr[0] * w0.x + gr[1] * w0.y + gr[2] * w0.z + gr[3] * w0.w
                      + gr[4] * w1.x + gr[5] * w1.y + gr[6] * w1.z + gr[7] * w1.w
                      + gr[8] * w2.x + gr[9] * w2.y + gr[10]* w2.z + gr[11]* w2.w
                      + gr[12]* w3.x + gr[13]* w3.y + gr[14]* w3.z + gr[15]* w3.w;
            #pragma unroll
            for (int v = 0; v < 5; v++)
                e2[v] += Xs[(ml * 5 + v) * X2P + node] * g2m;
        }
        __syncthreads();   // chunk reads done before restage
    }
    // combine the two m-halves within the thread pair
    #pragma unroll
    for (int v = 0; v < 5; v++)
        e2[v] += __shfl_xor_sync(FULLMASK, e2[v], 1);

    // ---- per-node source vector + segment sum ----
    float s0 = sS[node * 2 + 0];
    float s1 = sS[node * 2 + 1];
    float e0 = sE0[node];
    float v6[6];
    v6[0] = valid ? (e0 * s0) : 0.f;
    #pragma unroll
    for (int v = 0; v < 5; v++) v6[v + 1] = valid ? (e2[v] * s1) : 0.f;

    int g  = valid ? batch[gnode] : -1;
    int g0 = __shfl_sync(FULLMASK, g, 0);
    bool uni = __all_sync(FULLMASK, g == g0);
    if (uni) {
        #pragma unroll
        for (int d = 0; d < 6; d++) {
            float t = half ? 0.f : v6[d];   // avoid double count across lane pairs
            #pragma unroll
            for (int o = 16; o > 0; o >>= 1) t += __shfl_xor_sync(FULLMASK, t, o);
            if ((tid & 31) == 0 && g0 >= 0) atomicAdd(&g_polar[g0 * 6 + d], t);
        }
    } else if (g >= 0 && half == 0) {
        #pragma unroll
        for (int d = 0; d < 6; d++) atomicAdd(&g_polar[g * 6 + d], v6[d]);
    }

    // ===================== last-block finalize =====================
    __shared__ unsigned s_ticket;
    __threadfence();
    __syncthreads();
    if (tid == 0) s_ticket = atomicAdd(&g_done, 1u);
    __syncthreads();
    if (s_ticket == gridDim.x - 1) {
        __threadfence();
        for (int gg = tid; gg < G; gg += TB) {
            float zero  = g_polar[gg * 6 + 0];
            float dxy   = g_polar[gg * 6 + 1];
            float dyz   = g_polar[gg * 6 + 2];
            float dz2   = g_polar[gg * 6 + 3];
            float dzx   = g_polar[gg * 6 + 4];
            float dx2y2 = g_polar[gg * 6 + 5];
            float dn = sqrtf(dxy*dxy + dyz*dyz + dz2*dz2 + dzx*dzx + dx2y2*dx2y2);
            const float cc = 0.5773502691896258f;
            float a00 = zero + cc * (dn - dz2) + dx2y2;
            float a11 = zero + cc * (dn - dz2) - dx2y2;
            float a22 = zero + cc * (dn + 2.0f * dz2);
            out[gg * 9 + 0] = a00; out[gg * 9 + 1] = dxy; out[gg * 9 + 2] = dzx;
            out[gg * 9 + 3] = dxy; out[gg * 9 + 4] = a11; out[gg * 9 + 5] = dyz;
            out[gg * 9 + 6] = dzx; out[gg * 9 + 7] = dyz; out[gg * 9 + 8] = a22;
            #pragma unroll
            for (int d = 0; d < 6; d++) g_polar[gg * 6 + d] = 0.f;  // reset for next call
        }
        if (tid == 0) g_done = 0;  // reset ticket for next call
    }
}

// ================= launch =================
extern "C" void kernel_launch(void* const* d_in, const int* in_sizes, int n_in,
                              void* d_out, int out_size)
{
    const float* ns    = (const float*)d_in[0];
    const float* ne    = (const float*)d_in[1];
    const int*   batch = (const int*)d_in[2];
    // n_graphs may or may not be materialized as a scalar input: detect by size.
    int wb = (n_in > 3 && in_sizes[3] == 128 * 64) ? 3 : 4;
    const float* W_s1 = (const float*)d_in[wb + 0];
    const float* b_s1 = (const float*)d_in[wb + 1];
    const float* W_s2 = (const float*)d_in[wb + 2];
    const float* b_s2 = (const float*)d_in[wb + 3];
    const float* W_e0 = (const float*)d_in[wb + 4];
    const float* b_e0 = (const float*)d_in[wb + 5];
    const float* W_e2 = (const float*)d_in[wb + 6];
    const float* W_g  = (const float*)d_in[wb + 7];
    const float* b_g  = (const float*)d_in[wb + 8];
    const float* W_o0 = (const float*)d_in[wb + 9];
    const float* b_o0 = (const float*)d_in[wb + 10];
    const float* W_o2 = (const float*)d_in[wb + 11];

    int N = in_sizes[0] / 128;
    int G = out_size / 9;

    size_t smemBytes = (size_t)SM_FLOATS * sizeof(float);
    cudaFuncSetAttribute(main_kernel, cudaFuncAttributeMaxDynamicSharedMemorySize,
                         (int)smemBytes);
    int blocks = (N + TILE - 1) / TILE;
    main_kernel<<<blocks, TB, smemBytes>>>(ns, ne, batch, W_s1, b_s1,
                                           W_s2, b_s2, W_e0, b_e0, W_e2,
                                           W_g, b_g, W_o0, b_o0, W_o2,
                                           (float*)d_out, N, G);
}

// round 5
// speedup vs baseline: 1.2210x; 1.0118x over previous
#include <cuda_runtime.h>
#include <cstdint>

#define FULLMASK 0xFFFFFFFFu
#define TB   512
#define TILE 256
#define ROWP 132   // Xs row stride (128 + pad) -> conflict-free strided reads
#define X2P  258   // x2s column stride -> conflict-free reads

// ---- device scratch (no allocations allowed) ----
__device__ float    g_polar[4096 * 6];   // zero-initialized at load; re-zeroed by finalize
__device__ unsigned g_done;              // zero-initialized; reset by finalize

__device__ __forceinline__ float sigmoidf_(float x) {
    return __fdividef(1.0f, 1.0f + __expf(-x));
}
__device__ __forceinline__ float2 unpack2_(unsigned long long a) {
    float2 r;
    r.x = __uint_as_float((unsigned)(a & 0xffffffffull));
    r.y = __uint_as_float((unsigned)(a >> 32));
    return r;
}
__device__ __forceinline__ unsigned long long dup2_(float x) {
    unsigned long long d;
    unsigned xb = __float_as_uint(x);
    asm("mov.b64 %0, {%1, %1};" : "=l"(d) : "r"(xb));
    return d;
}
__device__ __forceinline__ void ffma2_(unsigned long long& acc,
                                       unsigned long long a,
                                       unsigned long long b) {
    asm("fma.rn.f32x2 %0, %1, %2, %0;" : "+l"(acc) : "l"(a), "l"(b));
}

// smem layout (floats): same as R2
#define SM_FLOATS 54612

__global__ void __launch_bounds__(TB, 1)
main_kernel(const float* __restrict__ ns, const float* __restrict__ ne,
            const int* __restrict__ batch,
            const float* __restrict__ W1,  const float* __restrict__ b1,
            const float* __restrict__ Ws2, const float* __restrict__ bs2,
            const float* __restrict__ We0, const float* __restrict__ be0,
            const float* __restrict__ We2, const float* __restrict__ Wg,
            const float* __restrict__ bg,  const float* __restrict__ Wo0,
            const float* __restrict__ bo0, const float* __restrict__ Wo2,
            float* __restrict__ out, int Ntot, int G)
{
    extern __shared__ float sm[];
    float* Xs   = sm;
    float* sW1  = sm + 33792;
    float* sW2  = sm + 41984;
    float* sWg  = sm + 52224;
    float* sWs2 = sm + 53248;
    float* sWc  = sm + 53376;
    float* sWo0 = sm + 53888;
    float* sB1  = sm + 53952;
    float* sB2  = sm + 54016;
    float* sMisc= sm + 54096;
    float* sS   = sm + 54100;
    float* sGate= sm + 20736;   // inside Xs region (valid after GEMM2)
    float* sE0  = sm + 25088;   // inside Xs region

    const int tid  = threadIdx.x;
    const int n    = tid >> 3;     // 0..63  (node sub-index)
    const int c    = tid & 7;      // 0..7   (column group: owns cols 4c..4c+3, 32+4c..32+4c+3)
    const int base = blockIdx.x * TILE;

    // ---- stage weights ----
    for (int i = tid; i < 8192; i += TB) sW1[i] = W1[i];
    for (int i = tid; i < 8192; i += TB) {
        int r = i >> 6, cc = i & 63;
        sW2[r * 80 + cc] = We0[i];
    }
    for (int i = tid; i < 1024; i += TB) sWg[i] = Wg[i];
    if (tid < 128) sWs2[tid] = Ws2[tid];
    if (tid < 512) sWc[tid] = We2[tid] * Wo2[tid & 15];
    if (tid < 64) { sWo0[tid] = Wo0[tid]; sB1[tid] = b1[tid]; sB2[tid] = be0[tid]; }
    if (tid == 0) { sMisc[0] = bs2[0]; sMisc[1] = bs2[1]; sMisc[2] = bo0[0]; }
    __syncthreads();

    // ---- per-block fold: W_e0 @ W_g into sW2 cols 64..79; bias fold ----
    {
        int r  = tid >> 2;           // 0..127
        int g0 = (tid & 3) * 4;      // 0,4,8,12
        float s0 = 0.f, s1 = 0.f, s2 = 0.f, s3 = 0.f;
        #pragma unroll 8
        for (int j = 0; j < 64; j++) {
            float x = sW2[r * 80 + j];
            float4 w = *(const float4*)&sWg[j * 16 + g0];
            s0 += x * w.x; s1 += x * w.y; s2 += x * w.z; s3 += x * w.w;
        }
        sW2[r * 80 + 64 + g0 + 0] = s0;
        sW2[r * 80 + 64 + g0 + 1] = s1;
        sW2[r * 80 + 64 + g0 + 2] = s2;
        sW2[r * 80 + 64 + g0 + 3] = s3;
        if (tid < 16) {
            float s = bg[tid];
            for (int j = 0; j < 64; j++) s += sB2[j] * sWg[j * 16 + tid];
            sB2[64 + tid] = s;
        }
    }

    // ---- stage node_scalar tile (float4, coalesced) ----
    for (int i = tid; i < TILE * 32; i += TB) {
        int node = i >> 5, q = i & 31;
        int gn = base + node;
        float4 v = (gn < Ntot) ? ((const float4*)ns)[gn * 32 + q]
                               : make_float4(0.f, 0.f, 0.f, 0.f);
        *(float4*)&Xs[node * ROWP + q * 4] = v;
    }
    __syncthreads();

    // ===================== GEMM1: ns @ W_s1 (64 cols) =====================
    // acc1[i][2g+p] holds col pair (4c + 32g + 2p, +1) for node n + 64*i
    unsigned long long acc1[4][4];
    #pragma unroll
    for (int i = 0; i < 4; i++)
        #pragma unroll
        for (int u = 0; u < 4; u++) acc1[i][u] = 0ull;

    #pragma unroll 4
    for (int k2 = 0; k2 < 128; k2 += 2) {
        ulonglong2 w00 = *(const ulonglong2*)&sW1[k2 * 64 + 4 * c];
        ulonglong2 w01 = *(const ulonglong2*)&sW1[k2 * 64 + 4 * c + 32];
        ulonglong2 w10 = *(const ulonglong2*)&sW1[(k2 + 1) * 64 + 4 * c];
        ulonglong2 w11 = *(const ulonglong2*)&sW1[(k2 + 1) * 64 + 4 * c + 32];
        #pragma unroll
        for (int i = 0; i < 4; i++) {
            float2 xp = *(const float2*)&Xs[(n + 64 * i) * ROWP + k2];
            unsigned long long x0 = dup2_(xp.x);
            unsigned long long x1 = dup2_(xp.y);
            ffma2_(acc1[i][0], w00.x, x0);
            ffma2_(acc1[i][1], w00.y, x0);
            ffma2_(acc1[i][2], w01.x, x0);
            ffma2_(acc1[i][3], w01.y, x0);
            ffma2_(acc1[i][0], w10.x, x1);
            ffma2_(acc1[i][1], w10.y, x1);
            ffma2_(acc1[i][2], w11.x, x1);
            ffma2_(acc1[i][3], w11.y, x1);
        }
    }
    __syncthreads();   // all Xs reads done before reload

    // ---- epilogue 1: s = silu(h1) @ W_s2 + b_s2 ----
    #pragma unroll
    for (int i = 0; i < 4; i++) {
        float sp0 = 0.f, sp1 = 0.f;
        #pragma unroll
        for (int u = 0; u < 4; u++) {
            int col = 4 * c + 32 * (u >> 1) + 2 * (u & 1);
            float2 h2 = unpack2_(acc1[i][u]);
            float h = h2.x + sB1[col];
            float hs = h * sigmoidf_(h);
            sp0 += hs * sWs2[col * 2 + 0];
            sp1 += hs * sWs2[col * 2 + 1];
            h = h2.y + sB1[col + 1];
            hs = h * sigmoidf_(h);
            sp0 += hs * sWs2[(col + 1) * 2 + 0];
            sp1 += hs * sWs2[(col + 1) * 2 + 1];
        }
        #pragma unroll
        for (int o = 1; o < 8; o <<= 1) {
            sp0 += __shfl_xor_sync(FULLMASK, sp0, o);
            sp1 += __shfl_xor_sync(FULLMASK, sp1, o);
        }
        if (c == 0) {
            int node = n + 64 * i;
            sS[node * 2 + 0] = sp0 + sMisc[0];
            sS[node * 2 + 1] = sp1 + sMisc[1];
        }
    }

    // ---- stage x0 tile (node_equi cols 0..127) ----
    for (int i = tid; i < TILE * 32; i += TB) {
        int node = i >> 5, q = i & 31;
        int gn = base + node;
        float4 v = (gn < Ntot) ? ((const float4*)ne)[gn * 120 + q]
                               : make_float4(0.f, 0.f, 0.f, 0.f);
        *(float4*)&Xs[node * ROWP + q * 4] = v;
    }
    __syncthreads();

    // ===================== GEMM2: x0 @ [W_e0 | W_e0@W_g] (80 cols) =====================
    // acc2[i][2g+p]: col pair (4c+32g+2p, +1); acc2[i][4]: gate pair (64+2c, +1)
    unsigned long long acc2[4][5];
    #pragma unroll
    for (int i = 0; i < 4; i++)
        #pragma unroll
        for (int u = 0; u < 5; u++) acc2[i][u] = 0ull;

    #pragma unroll 2
    for (int k2 = 0; k2 < 128; k2 += 2) {
        ulonglong2 w00 = *(const ulonglong2*)&sW2[k2 * 80 + 4 * c];
        ulonglong2 w01 = *(const ulonglong2*)&sW2[k2 * 80 + 4 * c + 32];
        unsigned long long wg0 = *(const unsigned long long*)&sW2[k2 * 80 + 64 + 2 * c];
        ulonglong2 w10 = *(const ulonglong2*)&sW2[(k2 + 1) * 80 + 4 * c];
        ulonglong2 w11 = *(const ulonglong2*)&sW2[(k2 + 1) * 80 + 4 * c + 32];
        unsigned long long wg1 = *(const unsigned long long*)&sW2[(k2 + 1) * 80 + 64 + 2 * c];
        #pragma unroll
        for (int i = 0; i < 4; i++) {
            float2 xp = *(const float2*)&Xs[(n + 64 * i) * ROWP + k2];
            unsigned long long x0 = dup2_(xp.x);
            unsigned long long x1 = dup2_(xp.y);
            ffma2_(acc2[i][0], w00.x, x0);
            ffma2_(acc2[i][1], w00.y, x0);
            ffma2_(acc2[i][2], w01.x, x0);
            ffma2_(acc2[i][3], w01.y, x0);
            ffma2_(acc2[i][4], wg0,   x0);
            ffma2_(acc2[i][0], w10.x, x1);
            ffma2_(acc2[i][1], w10.y, x1);
            ffma2_(acc2[i][2], w11.x, x1);
            ffma2_(acc2[i][3], w11.y, x1);
            ffma2_(acc2[i][4], wg1,   x1);
        }
    }
    __syncthreads();   // all Xs reads done before gate/e0 writes into Xs region

    // ---- epilogue 2: e0 partial + gate (gate cols fully owned per thread) ----
    #pragma unroll
    for (int i = 0; i < 4; i++) {
        int node = n + 64 * i;
        float e0p = 0.f;
        #pragma unroll
        for (int u = 0; u < 4; u++) {
            int col = 4 * c + 32 * (u >> 1) + 2 * (u & 1);
            float2 h2 = unpack2_(acc2[i][u]);
            float h = h2.x + sB2[col];
            e0p += (h * sigmoidf_(h)) * sWo0[col];
            h = h2.y + sB2[col + 1];
            e0p += (h * sigmoidf_(h)) * sWo0[col + 1];
        }
        {
            float2 gp = unpack2_(acc2[i][4]);
            sGate[node * 17 + 2 * c]     = sigmoidf_(gp.x + sB2[64 + 2 * c]);
            sGate[node * 17 + 2 * c + 1] = sigmoidf_(gp.y + sB2[64 + 2 * c + 1]);
        }
        #pragma unroll
        for (int o = 1; o < 8; o <<= 1)
            e0p += __shfl_xor_sync(FULLMASK, e0p, o);
        if (c == 0) sE0[node] = e0p + sMisc[2];
    }
    __syncthreads();

    // ===================== x2 contraction: e2[v] = sum_m x2[m,v] * g2[m] =====================
    // Thread pair (2t, 2t+1) shares node t; halves split the m-range.
    const int node = tid >> 1;
    const int half = tid & 1;
    float gr[16];
    #pragma unroll
    for (int h = 0; h < 16; h++) gr[h] = sGate[node * 17 + h];

    float e2[5] = {0.f, 0.f, 0.f, 0.f, 0.f};
    const int gnode = base + node;
    const bool valid = (gnode < Ntot);

    #pragma unroll
    for (int chunk = 0; chunk < 2; chunk++) {
        // cooperative transposed stage: x2s[col][node], 80 cols of this chunk (float4 loads)
        for (int i = tid; i < TILE * 20; i += TB) {
            int nd   = i / 20;
            int col4 = i - nd * 20;
            int gn   = base + nd;
            float4 v = (gn < Ntot)
                ? ((const float4*)ne)[gn * 120 + 80 + chunk * 20 + col4]
                : make_float4(0.f, 0.f, 0.f, 0.f);
            Xs[(col4 * 4 + 0) * X2P + nd] = v.x;
            Xs[(col4 * 4 + 1) * X2P + nd] = v.y;
            Xs[(col4 * 4 + 2) * X2P + nd] = v.z;
            Xs[(col4 * 4 + 3) * X2P + nd] = v.w;
        }
        __syncthreads();
        #pragma unroll
        for (int mm = 0; mm < 8; mm++) {
            int ml = half * 8 + mm;              // local m within chunk (0..15)
            int m  = chunk * 16 + ml;            // global m (0..31)
            const float4* wc = (const float4*)&sWc[m * 16];
            float4 w0 = wc[0], w1 = wc[1], w2 = wc[2], w3 = wc[3];
            float g2m = gr[0] * w0.x + gr[1] * w0.y + gr[2] * w0.z + gr[3] * w0.w
                      + gr[4] * w1.x + gr[5] * w1.y + gr[6] * w1.z + gr[7] * w1.w
                      + gr[8] * w2.x + gr[9] * w2.y + gr[10]* w2.z + gr[11]* w2.w
                      + gr[12]* w3.x + gr[13]* w3.y + gr[14]* w3.z + gr[15]* w3.w;
            #pragma unroll
            for (int v = 0; v < 5; v++)
                e2[v] += Xs[(ml * 5 + v) * X2P + node] * g2m;
        }
        __syncthreads();   // chunk reads done before restage
    }
    // combine the two m-halves within the thread pair
    #pragma unroll
    for (int v = 0; v < 5; v++)
        e2[v] += __shfl_xor_sync(FULLMASK, e2[v], 1);

    // ---- per-node source vector + segment sum ----
    float s0 = sS[node * 2 + 0];
    float s1 = sS[node * 2 + 1];
    float e0 = sE0[node];
    float v6[6];
    v6[0] = valid ? (e0 * s0) : 0.f;
    #pragma unroll
    for (int v = 0; v < 5; v++) v6[v + 1] = valid ? (e2[v] * s1) : 0.f;

    int g  = valid ? batch[gnode] : -1;
    int g0 = __shfl_sync(FULLMASK, g, 0);
    bool uni = __all_sync(FULLMASK, g == g0);
    if (uni) {
        #pragma unroll
        for (int d = 0; d < 6; d++) {
            float t = half ? 0.f : v6[d];   // avoid double count across lane pairs
            #pragma unroll
            for (int o = 16; o > 0; o >>= 1) t += __shfl_xor_sync(FULLMASK, t, o);
            if ((tid & 31) == 0 && g0 >= 0) atomicAdd(&g_polar[g0 * 6 + d], t);
        }
    } else if (g >= 0 && half == 0) {
        #pragma unroll
        for (int d = 0; d < 6; d++) atomicAdd(&g_polar[g * 6 + d], v6[d]);
    }

    // ===================== last-block finalize =====================
    __shared__ unsigned s_ticket;
    __threadfence();
    __syncthreads();
    if (tid == 0) s_ticket = atomicAdd(&g_done, 1u);
    __syncthreads();
    if (s_ticket == gridDim.x - 1) {
        __threadfence();
        for (int gg = tid; gg < G; gg += TB) {
            float zero  = g_polar[gg * 6 + 0];
            float dxy   = g_polar[gg * 6 + 1];
            float dyz   = g_polar[gg * 6 + 2];
            float dz2   = g_polar[gg * 6 + 3];
            float dzx   = g_polar[gg * 6 + 4];
            float dx2y2 = g_polar[gg * 6 + 5];
            float dn = sqrtf(dxy*dxy + dyz*dyz + dz2*dz2 + dzx*dzx + dx2y2*dx2y2);
            const float cc = 0.5773502691896258f;
            float a00 = zero + cc * (dn - dz2) + dx2y2;
            float a11 = zero + cc * (dn - dz2) - dx2y2;
            float a22 = zero + cc * (dn + 2.0f * dz2);
            out[gg * 9 + 0] = a00; out[gg * 9 + 1] = dxy; out[gg * 9 + 2] = dzx;
            out[gg * 9 + 3] = dxy; out[gg * 9 + 4] = a11; out[gg * 9 + 5] = dyz;
            out[gg * 9 + 6] = dzx; out[gg * 9 + 7] = dyz; out[gg * 9 + 8] = a22;
            #pragma unroll
            for (int d = 0; d < 6; d++) g_polar[gg * 6 + d] = 0.f;  // reset for next call
        }
        if (tid == 0) g_done = 0;  // reset ticket for next call
    }
}

// ================= launch =================
extern "C" void kernel_launch(void* const* d_in, const int* in_sizes, int n_in,
                              void* d_out, int out_size)
{
    const float* ns    = (const float*)d_in[0];
    const float* ne    = (const float*)d_in[1];
    const int*   batch = (const int*)d_in[2];
    // n_graphs may or may not be materialized as a scalar input: detect by size.
    int wb = (n_in > 3 && in_sizes[3] == 128 * 64) ? 3 : 4;
    const float* W_s1 = (const float*)d_in[wb + 0];
    const float* b_s1 = (const float*)d_in[wb + 1];
    const float* W_s2 = (const float*)d_in[wb + 2];
    const float* b_s2 = (const float*)d_in[wb + 3];
    const float* W_e0 = (const float*)d_in[wb + 4];
    const float* b_e0 = (const float*)d_in[wb + 5];
    const float* W_e2 = (const float*)d_in[wb + 6];
    const float* W_g  = (const float*)d_in[wb + 7];
    const float* b_g  = (const float*)d_in[wb + 8];
    const float* W_o0 = (const float*)d_in[wb + 9];
    const float* b_o0 = (const float*)d_in[wb + 10];
    const float* W_o2 = (const float*)d_in[wb + 11];

    int N = in_sizes[0] / 128;
    int G = out_size / 9;

    size_t smemBytes = (size_t)SM_FLOATS * sizeof(float);
    cudaFuncSetAttribute(main_kernel, cudaFuncAttributeMaxDynamicSharedMemorySize,
                         (int)smemBytes);
    int blocks = (N + TILE - 1) / TILE;
    main_kernel<<<blocks, TB, smemBytes>>>(ns, ne, batch, W_s1, b_s1,
                                           W_s2, b_s2, W_e0, b_e0, W_e2,
                                           W_g, b_g, W_o0, b_o0, W_o2,
                                           (float*)d_out, N, G);
}

// round 6
// speedup vs baseline: 1.2219x; 1.0007x over previous
#include <cuda_runtime.h>
#include <cstdint>

#define FULLMASK 0xFFFFFFFFu
#define TB   512
#define TILE 256
#define ROWP 132   // Xs row stride (128 + pad) -> conflict-free strided reads
#define X2P  258   // x2s column stride -> conflict-free reads

// ---- device scratch (no allocations allowed) ----
__device__ float    g_polar[4096 * 6];   // zero-initialized at load; re-zeroed by finalize
__device__ unsigned g_done;              // zero-initialized; reset by finalize

__device__ __forceinline__ float sigmoidf_(float x) {
    return __fdividef(1.0f, 1.0f + __expf(-x));
}
__device__ __forceinline__ float2 unpack2_(unsigned long long a) {
    float2 r;
    r.x = __uint_as_float((unsigned)(a & 0xffffffffull));
    r.y = __uint_as_float((unsigned)(a >> 32));
    return r;
}
__device__ __forceinline__ unsigned long long dup2_(float x) {
    unsigned long long d;
    unsigned xb = __float_as_uint(x);
    asm("mov.b64 %0, {%1, %1};" : "=l"(d) : "r"(xb));
    return d;
}
__device__ __forceinline__ void ffma2_(unsigned long long& acc,
                                       unsigned long long a,
                                       unsigned long long b) {
    asm("fma.rn.f32x2 %0, %1, %2, %0;" : "+l"(acc) : "l"(a), "l"(b));
}

// smem layout (floats): same as R2
#define SM_FLOATS 54612

__global__ void __launch_bounds__(TB, 1)
main_kernel(const float* __restrict__ ns, const float* __restrict__ ne,
            const int* __restrict__ batch,
            const float* __restrict__ W1,  const float* __restrict__ b1,
            const float* __restrict__ Ws2, const float* __restrict__ bs2,
            const float* __restrict__ We0, const float* __restrict__ be0,
            const float* __restrict__ We2, const float* __restrict__ Wg,
            const float* __restrict__ bg,  const float* __restrict__ Wo0,
            const float* __restrict__ bo0, const float* __restrict__ Wo2,
            float* __restrict__ out, int Ntot, int G)
{
    extern __shared__ float sm[];
    float* Xs   = sm;
    float* sW1  = sm + 33792;
    float* sW2  = sm + 41984;
    float* sWg  = sm + 52224;
    float* sWs2 = sm + 53248;
    float* sWc  = sm + 53376;
    float* sWo0 = sm + 53888;
    float* sB1  = sm + 53952;
    float* sB2  = sm + 54016;
    float* sMisc= sm + 54096;
    float* sS   = sm + 54100;
    float* sGate= sm + 20736;   // inside Xs region (valid after GEMM2)
    float* sE0  = sm + 25088;   // inside Xs region

    const int tid  = threadIdx.x;
    const int n    = tid >> 3;     // 0..63  (node sub-index)
    const int c    = tid & 7;      // 0..7   (column group: owns cols 4c..4c+3, 32+4c..32+4c+3)
    const int base = blockIdx.x * TILE;

    // ---- stage weights ----
    for (int i = tid; i < 8192; i += TB) sW1[i] = W1[i];
    for (int i = tid; i < 8192; i += TB) {
        int r = i >> 6, cc = i & 63;
        sW2[r * 80 + cc] = We0[i];
    }
    for (int i = tid; i < 1024; i += TB) sWg[i] = Wg[i];
    if (tid < 128) sWs2[tid] = Ws2[tid];
    if (tid < 512) sWc[tid] = We2[tid] * Wo2[tid & 15];
    if (tid < 64) { sWo0[tid] = Wo0[tid]; sB1[tid] = b1[tid]; sB2[tid] = be0[tid]; }
    if (tid == 0) { sMisc[0] = bs2[0]; sMisc[1] = bs2[1]; sMisc[2] = bo0[0]; }
    __syncthreads();

    // ---- per-block fold: W_e0 @ W_g into sW2 cols 64..79; bias fold ----
    {
        int r  = tid >> 2;           // 0..127
        int g0 = (tid & 3) * 4;      // 0,4,8,12
        float s0 = 0.f, s1 = 0.f, s2 = 0.f, s3 = 0.f;
        #pragma unroll 8
        for (int j = 0; j < 64; j++) {
            float x = sW2[r * 80 + j];
            float4 w = *(const float4*)&sWg[j * 16 + g0];
            s0 += x * w.x; s1 += x * w.y; s2 += x * w.z; s3 += x * w.w;
        }
        sW2[r * 80 + 64 + g0 + 0] = s0;
        sW2[r * 80 + 64 + g0 + 1] = s1;
        sW2[r * 80 + 64 + g0 + 2] = s2;
        sW2[r * 80 + 64 + g0 + 3] = s3;
        if (tid < 16) {
            float s = bg[tid];
            for (int j = 0; j < 64; j++) s += sB2[j] * sWg[j * 16 + tid];
            sB2[64 + tid] = s;
        }
    }

    // ---- stage node_scalar tile (float4, coalesced) ----
    for (int i = tid; i < TILE * 32; i += TB) {
        int node = i >> 5, q = i & 31;
        int gn = base + node;
        float4 v = (gn < Ntot) ? ((const float4*)ns)[gn * 32 + q]
                               : make_float4(0.f, 0.f, 0.f, 0.f);
        *(float4*)&Xs[node * ROWP + q * 4] = v;
    }
    __syncthreads();

    // ===================== GEMM1: ns @ W_s1 (64 cols) =====================
    // acc1[i][2g+p] holds col pair (4c + 32g + 2p, +1) for node n + 64*i
    unsigned long long acc1[4][4];
    #pragma unroll
    for (int i = 0; i < 4; i++)
        #pragma unroll
        for (int u = 0; u < 4; u++) acc1[i][u] = 0ull;

    #pragma unroll 4
    for (int k2 = 0; k2 < 128; k2 += 2) {
        ulonglong2 w00 = *(const ulonglong2*)&sW1[k2 * 64 + 4 * c];
        ulonglong2 w01 = *(const ulonglong2*)&sW1[k2 * 64 + 4 * c + 32];
        ulonglong2 w10 = *(const ulonglong2*)&sW1[(k2 + 1) * 64 + 4 * c];
        ulonglong2 w11 = *(const ulonglong2*)&sW1[(k2 + 1) * 64 + 4 * c + 32];
        #pragma unroll
        for (int i = 0; i < 4; i++) {
            float2 xp = *(const float2*)&Xs[(n + 64 * i) * ROWP + k2];
            unsigned long long x0 = dup2_(xp.x);
            unsigned long long x1 = dup2_(xp.y);
            ffma2_(acc1[i][0], w00.x, x0);
            ffma2_(acc1[i][1], w00.y, x0);
            ffma2_(acc1[i][2], w01.x, x0);
            ffma2_(acc1[i][3], w01.y, x0);
            ffma2_(acc1[i][0], w10.x, x1);
            ffma2_(acc1[i][1], w10.y, x1);
            ffma2_(acc1[i][2], w11.x, x1);
            ffma2_(acc1[i][3], w11.y, x1);
        }
    }
    __syncthreads();   // all Xs reads done before reload

    // ---- epilogue 1: s = silu(h1) @ W_s2 + b_s2 ----
    #pragma unroll
    for (int i = 0; i < 4; i++) {
        float sp0 = 0.f, sp1 = 0.f;
        #pragma unroll
        for (int u = 0; u < 4; u++) {
            int col = 4 * c + 32 * (u >> 1) + 2 * (u & 1);
            float2 h2 = unpack2_(acc1[i][u]);
            float h = h2.x + sB1[col];
            float hs = h * sigmoidf_(h);
            sp0 += hs * sWs2[col * 2 + 0];
            sp1 += hs * sWs2[col * 2 + 1];
            h = h2.y + sB1[col + 1];
            hs = h * sigmoidf_(h);
            sp0 += hs * sWs2[(col + 1) * 2 + 0];
            sp1 += hs * sWs2[(col + 1) * 2 + 1];
        }
        #pragma unroll
        for (int o = 1; o < 8; o <<= 1) {
            sp0 += __shfl_xor_sync(FULLMASK, sp0, o);
            sp1 += __shfl_xor_sync(FULLMASK, sp1, o);
        }
        if (c == 0) {
            int node = n + 64 * i;
            sS[node * 2 + 0] = sp0 + sMisc[0];
            sS[node * 2 + 1] = sp1 + sMisc[1];
        }
    }

    // ---- stage x0 tile (node_equi cols 0..127) ----
    for (int i = tid; i < TILE * 32; i += TB) {
        int node = i >> 5, q = i & 31;
        int gn = base + node;
        float4 v = (gn < Ntot) ? ((const float4*)ne)[gn * 120 + q]
                               : make_float4(0.f, 0.f, 0.f, 0.f);
        *(float4*)&Xs[node * ROWP + q * 4] = v;
    }
    __syncthreads();

    // ===================== GEMM2: x0 @ [W_e0 | W_e0@W_g] (80 cols) =====================
    // acc2[i][2g+p]: col pair (4c+32g+2p, +1); acc2[i][4]: gate pair (64+2c, +1)
    unsigned long long acc2[4][5];
    #pragma unroll
    for (int i = 0; i < 4; i++)
        #pragma unroll
        for (int u = 0; u < 5; u++) acc2[i][u] = 0ull;

    #pragma unroll 2
    for (int k2 = 0; k2 < 128; k2 += 2) {
        ulonglong2 w00 = *(const ulonglong2*)&sW2[k2 * 80 + 4 * c];
        ulonglong2 w01 = *(const ulonglong2*)&sW2[k2 * 80 + 4 * c + 32];
        unsigned long long wg0 = *(const unsigned long long*)&sW2[k2 * 80 + 64 + 2 * c];
        ulonglong2 w10 = *(const ulonglong2*)&sW2[(k2 + 1) * 80 + 4 * c];
        ulonglong2 w11 = *(const ulonglong2*)&sW2[(k2 + 1) * 80 + 4 * c + 32];
        unsigned long long wg1 = *(const unsigned long long*)&sW2[(k2 + 1) * 80 + 64 + 2 * c];
        #pragma unroll
        for (int i = 0; i < 4; i++) {
            float2 xp = *(const float2*)&Xs[(n + 64 * i) * ROWP + k2];
            unsigned long long x0 = dup2_(xp.x);
            unsigned long long x1 = dup2_(xp.y);
            ffma2_(acc2[i][0], w00.x, x0);
            ffma2_(acc2[i][1], w00.y, x0);
            ffma2_(acc2[i][2], w01.x, x0);
            ffma2_(acc2[i][3], w01.y, x0);
            ffma2_(acc2[i][4], wg0,   x0);
            ffma2_(acc2[i][0], w10.x, x1);
            ffma2_(acc2[i][1], w10.y, x1);
            ffma2_(acc2[i][2], w11.x, x1);
            ffma2_(acc2[i][3], w11.y, x1);
            ffma2_(acc2[i][4], wg1,   x1);
        }
    }
    __syncthreads();   // all Xs reads done before gate/e0 writes into Xs region

    // ---- epilogue 2: e0 partial + gate (gate cols fully owned per thread) ----
    #pragma unroll
    for (int i = 0; i < 4; i++) {
        int node = n + 64 * i;
        float e0p = 0.f;
        #pragma unroll
        for (int u = 0; u < 4; u++) {
            int col = 4 * c + 32 * (u >> 1) + 2 * (u & 1);
            float2 h2 = unpack2_(acc2[i][u]);
            float h = h2.x + sB2[col];
            e0p += (h * sigmoidf_(h)) * sWo0[col];
            h = h2.y + sB2[col + 1];
            e0p += (h * sigmoidf_(h)) * sWo0[col + 1];
        }
        {
            float2 gp = unpack2_(acc2[i][4]);
            sGate[node * 17 + 2 * c]     = sigmoidf_(gp.x + sB2[64 + 2 * c]);
            sGate[node * 17 + 2 * c + 1] = sigmoidf_(gp.y + sB2[64 + 2 * c + 1]);
        }
        #pragma unroll
        for (int o = 1; o < 8; o <<= 1)
            e0p += __shfl_xor_sync(FULLMASK, e0p, o);
        if (c == 0) sE0[node] = e0p + sMisc[2];
    }
    __syncthreads();

    // ===================== x2 contraction: e2[v] = sum_m x2[m,v] * g2[m] =====================
    // Thread pair (2t, 2t+1) shares node t; halves split the m-range.
    const int node = tid >> 1;
    const int half = tid & 1;
    float gr[16];
    #pragma unroll
    for (int h = 0; h < 16; h++) gr[h] = sGate[node * 17 + h];

    float e2[5] = {0.f, 0.f, 0.f, 0.f, 0.f};
    const int gnode = base + node;
    const bool valid = (gnode < Ntot);

    #pragma unroll
    for (int chunk = 0; chunk < 2; chunk++) {
        // cooperative transposed stage: x2s[col][node], 80 cols of this chunk (float4 loads)
        for (int i = tid; i < TILE * 20; i += TB) {
            int nd   = i / 20;
            int col4 = i - nd * 20;
            int gn   = base + nd;
            float4 v = (gn < Ntot)
                ? ((const float4*)ne)[gn * 120 + 80 + chunk * 20 + col4]
                : make_float4(0.f, 0.f, 0.f, 0.f);
            Xs[(col4 * 4 + 0) * X2P + nd] = v.x;
            Xs[(col4 * 4 + 1) * X2P + nd] = v.y;
            Xs[(col4 * 4 + 2) * X2P + nd] = v.z;
            Xs[(col4 * 4 + 3) * X2P + nd] = v.w;
        }
        __syncthreads();
        #pragma unroll
        for (int mm = 0; mm < 8; mm++) {
            int ml = half * 8 + mm;              // local m within chunk (0..15)
            int m  = chunk * 16 + ml;            // global m (0..31)
            const float4* wc = (const float4*)&sWc[m * 16];
            float4 w0 = wc[0], w1 = wc[1], w2 = wc[2], w3 = wc[3];
            float g2m = gr[0] * w0.x + gr[1] * w0.y + gr[2] * w0.z + gr[3] * w0.w
                      + gr[4] * w1.x + gr[5] * w1.y + gr[6] * w1.z + gr[7] * w1.w
                      + gr[8] * w2.x + gr[9] * w2.y + gr[10]* w2.z + gr[11]* w2.w
                      + gr[12]* w3.x + gr[13]* w3.y + gr[14]* w3.z + gr[15]* w3.w;
            #pragma unroll
            for (int v = 0; v < 5; v++)
                e2[v] += Xs[(ml * 5 + v) * X2P + node] * g2m;
        }
        __syncthreads();   // chunk reads done before restage
    }
    // combine the two m-halves within the thread pair
    #pragma unroll
    for (int v = 0; v < 5; v++)
        e2[v] += __shfl_xor_sync(FULLMASK, e2[v], 1);

    // ---- per-node source vector + segment sum ----
    float s0 = sS[node * 2 + 0];
    float s1 = sS[node * 2 + 1];
    float e0 = sE0[node];
    float v6[6];
    v6[0] = valid ? (e0 * s0) : 0.f;
    #pragma unroll
    for (int v = 0; v < 5; v++) v6[v + 1] = valid ? (e2[v] * s1) : 0.f;

    int g  = valid ? batch[gnode] : -1;
    int g0 = __shfl_sync(FULLMASK, g, 0);
    bool uni = __all_sync(FULLMASK, g == g0);
    if (uni) {
        #pragma unroll
        for (int d = 0; d < 6; d++) {
            float t = half ? 0.f : v6[d];   // avoid double count across lane pairs
            #pragma unroll
            for (int o = 16; o > 0; o >>= 1) t += __shfl_xor_sync(FULLMASK, t, o);
            if ((tid & 31) == 0 && g0 >= 0) atomicAdd(&g_polar[g0 * 6 + d], t);
        }
    } else if (g >= 0 && half == 0) {
        #pragma unroll
        for (int d = 0; d < 6; d++) atomicAdd(&g_polar[g * 6 + d], v6[d]);
    }

    // ===================== last-block finalize =====================
    __shared__ unsigned s_ticket;
    __threadfence();
    __syncthreads();
    if (tid == 0) s_ticket = atomicAdd(&g_done, 1u);
    __syncthreads();
    if (s_ticket == gridDim.x - 1) {
        __threadfence();
        for (int gg = tid; gg < G; gg += TB) {
            float zero  = g_polar[gg * 6 + 0];
            float dxy   = g_polar[gg * 6 + 1];
            float dyz   = g_polar[gg * 6 + 2];
            float dz2   = g_polar[gg * 6 + 3];
            float dzx   = g_polar[gg * 6 + 4];
            float dx2y2 = g_polar[gg * 6 + 5];
            float dn = sqrtf(dxy*dxy + dyz*dyz + dz2*dz2 + dzx*dzx + dx2y2*dx2y2);
            const float cc = 0.5773502691896258f;
            float a00 = zero + cc * (dn - dz2) + dx2y2;
            float a11 = zero + cc * (dn - dz2) - dx2y2;
            float a22 = zero + cc * (dn + 2.0f * dz2);
            out[gg * 9 + 0] = a00; out[gg * 9 + 1] = dxy; out[gg * 9 + 2] = dzx;
            out[gg * 9 + 3] = dxy; out[gg * 9 + 4] = a11; out[gg * 9 + 5] = dyz;
            out[gg * 9 + 6] = dzx; out[gg * 9 + 7] = dyz; out[gg * 9 + 8] = a22;
            #pragma unroll
            for (int d = 0; d < 6; d++) g_polar[gg * 6 + d] = 0.f;  // reset for next call
        }
        if (tid == 0) g_done = 0;  // reset ticket for next call
    }
}

// ================= launch =================
extern "C" void kernel_launch(void* const* d_in, const int* in_sizes, int n_in,
                              void* d_out, int out_size)
{
    const float* ns    = (const float*)d_in[0];
    const float* ne    = (const float*)d_in[1];
    const int*   batch = (const int*)d_in[2];
    // n_graphs may or may not be materialized as a scalar input: detect by size.
    int wb = (n_in > 3 && in_sizes[3] == 128 * 64) ? 3 : 4;
    const float* W_s1 = (const float*)d_in[wb + 0];
    const float* b_s1 = (const float*)d_in[wb + 1];
    const float* W_s2 = (const float*)d_in[wb + 2];
    const float* b_s2 = (const float*)d_in[wb + 3];
    const float* W_e0 = (const float*)d_in[wb + 4];
    const float* b_e0 = (const float*)d_in[wb + 5];
    const float* W_e2 = (const float*)d_in[wb + 6];
    const float* W_g  = (const float*)d_in[wb + 7];
    const float* b_g  = (const float*)d_in[wb + 8];
    const float* W_o0 = (const float*)d_in[wb + 9];
    const float* b_o0 = (const float*)d_in[wb + 10];
    const float* W_o2 = (const float*)d_in[wb + 11];

    int N = in_sizes[0] / 128;
    int G = out_size / 9;

    size_t smemBytes = (size_t)SM_FLOATS * sizeof(float);
    cudaFuncSetAttribute(main_kernel, cudaFuncAttributeMaxDynamicSharedMemorySize,
                         (int)smemBytes);
    int blocks = (N + TILE - 1) / TILE;
    main_kernel<<<blocks, TB, smemBytes>>>(ns, ne, batch, W_s1, b_s1,
                                           W_s2, b_s2, W_e0, b_e0, W_e2,
                                           W_g, b_g, W_o0, b_o0, W_o2,
                                           (float*)d_out, N, G);
}